// round 1
// baseline (speedup 1.0000x reference)
#include <cuda_runtime.h>
#include <cuda_bf16.h>
#include <cstdint>

// Problem constants
#define BATCH   16
#define TSTEPS  4096
#define DIMSZ   512
#define NST     64
#define MROWS   (BATCH * TSTEPS)      // 65536

// ---------------- scratch (device globals: allocation-free) ----------------
__device__ float          g_x   [(size_t)BATCH * TSTEPS * DIMSZ];   // normed x
__device__ __nv_bfloat16  g_yhi [(size_t)BATCH * TSTEPS * DIMSZ];
__device__ __nv_bfloat16  g_ylo [(size_t)BATCH * TSTEPS * DIMSZ];
__device__ float          g_A   [DIMSZ * NST];                      // A_bar
__device__ float          g_CB  [DIMSZ * NST];                      // C*B*dt
__device__ __nv_bfloat16  g_whi [DIMSZ * DIMSZ];
__device__ __nv_bfloat16  g_wlo [DIMSZ * DIMSZ];

// ---------------- packed f32x2 helpers ----------------
__device__ __forceinline__ unsigned long long pk2(float lo, float hi) {
    unsigned long long r;
    asm("mov.b64 %0, {%1,%2};" : "=l"(r) : "f"(lo), "f"(hi));
    return r;
}
__device__ __forceinline__ void upk2(unsigned long long v, float& lo, float& hi) {
    asm("mov.b64 {%0,%1}, %2;" : "=f"(lo), "=f"(hi) : "l"(v));
}
__device__ __forceinline__ unsigned long long mul2(unsigned long long a, unsigned long long b) {
    unsigned long long r;
    asm("mul.rn.f32x2 %0, %1, %2;" : "=l"(r) : "l"(a), "l"(b));
    return r;
}
__device__ __forceinline__ unsigned long long add2(unsigned long long a, unsigned long long b) {
    unsigned long long r;
    asm("add.rn.f32x2 %0, %1, %2;" : "=l"(r) : "l"(a), "l"(b));
    return r;
}
__device__ __forceinline__ unsigned long long fma2(unsigned long long a, unsigned long long b,
                                                   unsigned long long c) {
    unsigned long long r;
    asm("fma.rn.f32x2 %0, %1, %2, %3;" : "=l"(r) : "l"(a), "l"(b), "l"(c));
    return r;
}

// ---------------- cp.async / ldmatrix / mma helpers ----------------
__device__ __forceinline__ void cp16(void* dst, const void* src) {
    uint32_t d = (uint32_t)__cvta_generic_to_shared(dst);
    asm volatile("cp.async.cg.shared.global [%0], [%1], 16;\n" :: "r"(d), "l"(src) : "memory");
}
__device__ __forceinline__ void cp_commit() { asm volatile("cp.async.commit_group;\n" ::: "memory"); }
__device__ __forceinline__ void cp_wait1()  { asm volatile("cp.async.wait_group 1;\n" ::: "memory"); }
__device__ __forceinline__ void cp_wait0()  { asm volatile("cp.async.wait_group 0;\n" ::: "memory"); }

__device__ __forceinline__ void ldm_x4(uint32_t* r, const void* p) {
    uint32_t a = (uint32_t)__cvta_generic_to_shared(p);
    asm volatile("ldmatrix.sync.aligned.m8n8.x4.shared.b16 {%0,%1,%2,%3}, [%4];"
                 : "=r"(r[0]), "=r"(r[1]), "=r"(r[2]), "=r"(r[3]) : "r"(a));
}
__device__ __forceinline__ void ldm_x2(uint32_t* r, const void* p) {
    uint32_t a = (uint32_t)__cvta_generic_to_shared(p);
    asm volatile("ldmatrix.sync.aligned.m8n8.x2.shared.b16 {%0,%1}, [%2];"
                 : "=r"(r[0]), "=r"(r[1]) : "r"(a));
}
__device__ __forceinline__ void mma16816(float* c, const uint32_t* a, const uint32_t* b) {
    asm volatile("mma.sync.aligned.m16n8k16.row.col.f32.bf16.bf16.f32 "
                 "{%0,%1,%2,%3}, {%4,%5,%6,%7}, {%8,%9}, {%0,%1,%2,%3};"
                 : "+f"(c[0]), "+f"(c[1]), "+f"(c[2]), "+f"(c[3])
                 : "r"(a[0]), "r"(a[1]), "r"(a[2]), "r"(a[3]), "r"(b[0]), "r"(b[1]));
}

// ================== kernel 1: parameter discretization ==================
__global__ void __launch_bounds__(256)
prep_params_kernel(const float* __restrict__ A_log, const float* __restrict__ log_dt,
                   const float* __restrict__ B_in, const float* __restrict__ C_in) {
    int idx = blockIdx.x * 256 + threadIdx.x;      // 512*64 = 32768
    if (idx >= DIMSZ * NST) return;
    int d = idx >> 6;
    int n = idx & 63;
    float ld = log_dt[d];
    float dt = (ld > 15.f) ? ld : log1pf(expf(ld));   // softplus
    g_A[idx]  = expf(-dt * expf(A_log[idx]));
    g_CB[idx] = C_in[idx] * dt * B_in[n];
}

// ================== kernel 2: mixer weight bf16 split ==================
__global__ void __launch_bounds__(256)
prep_w_kernel(const float* __restrict__ W) {
    int idx = blockIdx.x * 256 + threadIdx.x;      // 262144
    float w = W[idx];
    __nv_bfloat16 h = __float2bfloat16(w);
    g_whi[idx] = h;
    g_wlo[idx] = __float2bfloat16(w - __bfloat162float(h));
}

// ================== kernel 3: RMSNorm ==================
__global__ void __launch_bounds__(256)
rmsnorm_kernel(const float* __restrict__ tokens, const float* __restrict__ nw) {
    int row  = blockIdx.x * 8 + (threadIdx.x >> 5);
    int lane = threadIdx.x & 31;
    const float* p = tokens + (size_t)row * DIMSZ;
    float4 v[4];
    float ss = 0.f;
#pragma unroll
    for (int j = 0; j < 4; j++) {
        v[j] = *(const float4*)(p + lane * 4 + j * 128);
        ss += v[j].x * v[j].x + v[j].y * v[j].y + v[j].z * v[j].z + v[j].w * v[j].w;
    }
#pragma unroll
    for (int off = 16; off > 0; off >>= 1)
        ss += __shfl_xor_sync(0xffffffffu, ss, off);
    float rs = rsqrtf(ss * (1.0f / 512.0f) + 1e-4f);
    float* xo = g_x + (size_t)row * DIMSZ;
#pragma unroll
    for (int j = 0; j < 4; j++) {
        float4 w4 = *(const float4*)(nw + lane * 4 + j * 128);
        float4 o;
        o.x = v[j].x * rs * w4.x;  o.y = v[j].y * rs * w4.y;
        o.z = v[j].z * rs * w4.z;  o.w = v[j].w * rs * w4.w;
        *(float4*)(xo + lane * 4 + j * 128) = o;
    }
}

// ================== kernel 4: the SSM scan ==================
// grid = 128 blocks (16 batches x 8 d-tiles of 64), 256 threads.
// thread: d_local = tid>>2 (0..63), slot = tid&3 owns 16 of the 64 states.
#define TC 64
__global__ void __launch_bounds__(256)
scan_kernel(const float* __restrict__ Din) {
    __shared__ float xs[TC][64];
    __shared__ float ysm[TC][64];
    int tid  = threadIdx.x;
    int b    = blockIdx.x >> 3;
    int d0   = (blockIdx.x & 7) << 6;
    int dl   = tid >> 2;
    int slot = tid & 3;
    int n0   = slot << 4;
    int d    = d0 + dl;

    unsigned long long a_[8], cb_[8], s_[8];
    const float2* ap = reinterpret_cast<const float2*>(g_A  + d * NST + n0);
    const float2* cp = reinterpret_cast<const float2*>(g_CB + d * NST + n0);
#pragma unroll
    for (int i = 0; i < 8; i++) {
        float2 t = ap[i]; a_[i]  = pk2(t.x, t.y);
        float2 u = cp[i]; cb_[i] = pk2(u.x, u.y);
        s_[i] = pk2(0.f, 0.f);
    }
    float dg = Din[d];

    const float* xg = g_x + (size_t)b * TSTEPS * DIMSZ + d0;
    int cj = tid & 63, cr0 = tid >> 6;           // cooperative copy mapping
    size_t mbase = (size_t)b * TSTEPS;

    for (int t0 = 0; t0 < TSTEPS; t0 += TC) {
#pragma unroll
        for (int i = 0; i < TC / 4; i++) {
            int r = cr0 + i * 4;
            xs[r][cj] = xg[(size_t)(t0 + r) * DIMSZ + cj];
        }
        __syncthreads();
#pragma unroll 4
        for (int tt = 0; tt < TC; tt++) {
            float xv = xs[tt][dl];
            unsigned long long xx = pk2(xv, xv);
#pragma unroll
            for (int p = 0; p < 8; p++) {
                unsigned long long u = mul2(a_[p], s_[p]);
                s_[p] = fma2(cb_[p], xx, u);
            }
            unsigned long long p0 = add2(s_[0], s_[1]);
            unsigned long long p1 = add2(s_[2], s_[3]);
            unsigned long long p2 = add2(s_[4], s_[5]);
            unsigned long long p3 = add2(s_[6], s_[7]);
            unsigned long long q0 = add2(p0, p1);
            unsigned long long q1 = add2(p2, p3);
            unsigned long long acc2 = add2(q0, q1);
            float al, ah;
            upk2(acc2, al, ah);
            float acc = al + ah;
            acc += __shfl_xor_sync(0xffffffffu, acc, 1);
            acc += __shfl_xor_sync(0xffffffffu, acc, 2);
            if (slot == 0) ysm[tt][dl] = fmaf(dg, xv, acc);
        }
        __syncthreads();
#pragma unroll
        for (int i = 0; i < TC / 4; i++) {
            int r = cr0 + i * 4;
            float v = ysm[r][cj];
            __nv_bfloat16 h = __float2bfloat16(v);
            __nv_bfloat16 l = __float2bfloat16(v - __bfloat162float(h));
            size_t idx = (mbase + t0 + r) * DIMSZ + d0 + cj;
            g_yhi[idx] = h;
            g_ylo[idx] = l;
        }
        __syncthreads();
    }
}

// ================== kernel 5: mixer GEMM (3-term bf16 split) + residual ==================
// out[m, e] = tokens[m, e] + sum_d y[m, d] * W[e, d] + bias[e]
// BM=128, BN=64, BK=16, 256 threads (8 warps as 4(M) x 2(N), warp tile 32x32)
__global__ void __launch_bounds__(256)
gemm_kernel(const float* __restrict__ tokens, const float* __restrict__ bias,
            float* __restrict__ out) {
    __shared__ __nv_bfloat16 sa[2][2][128 * 24];   // [stage][hi/lo][row*24 + k]
    __shared__ __nv_bfloat16 sb[2][2][64 * 24];

    int tid = threadIdx.x;
    int m0 = blockIdx.y * 128;
    int n0 = blockIdx.x * 64;

    float acc[2][4][4];
#pragma unroll
    for (int i = 0; i < 2; i++)
#pragma unroll
        for (int j = 0; j < 4; j++)
#pragma unroll
            for (int k = 0; k < 4; k++) acc[i][j][k] = 0.f;

    // cp.async assignments: A(hi&lo): row=tid>>1, chunk=tid&1 ; B: 128 thr each for hi/lo
    int arow = tid >> 1, ach = tid & 1;
    size_t a_goff = (size_t)(m0 + arow) * DIMSZ + ach * 8;
    int a_soff = arow * 24 + ach * 8;
    int t2 = tid & 127, sel = tid >> 7;
    int brow = t2 >> 1, bch = t2 & 1;
    size_t b_goff = (size_t)(n0 + brow) * DIMSZ + bch * 8;
    int b_soff = brow * 24 + bch * 8;
    const __nv_bfloat16* wsrc = sel ? g_wlo : g_whi;

    auto load_st = [&](int st, int k0) {
        cp16(&sa[st][0][a_soff], g_yhi + a_goff + k0);
        cp16(&sa[st][1][a_soff], g_ylo + a_goff + k0);
        cp16(&sb[st][sel][b_soff], wsrc + b_goff + k0);
        cp_commit();
    };
    load_st(0, 0);

    int lane = tid & 31;
    int wid  = tid >> 5;
    int m_off = (wid & 3) * 32;
    int n_off = (wid >> 2) * 32;
    int a_lrow = lane & 15, a_lk = (lane >> 4) * 8;
    int b_lrow = lane & 7,  b_lk = ((lane >> 3) & 1) * 8;

    for (int kt = 0; kt < 32; kt++) {
        int cur = kt & 1;
        if (kt < 31) {
            load_st(cur ^ 1, (kt + 1) * 16);
            cp_wait1();
        } else {
            cp_wait0();
        }
        __syncthreads();

        uint32_t ah[2][4], al[2][4], bh[4][2], bl[4][2];
#pragma unroll
        for (int tm = 0; tm < 2; tm++) {
            int r = (m_off + tm * 16 + a_lrow) * 24 + a_lk;
            ldm_x4(ah[tm], &sa[cur][0][r]);
            ldm_x4(al[tm], &sa[cur][1][r]);
        }
#pragma unroll
        for (int tn = 0; tn < 4; tn++) {
            int r = (n_off + tn * 8 + b_lrow) * 24 + b_lk;
            ldm_x2(bh[tn], &sb[cur][0][r]);
            ldm_x2(bl[tn], &sb[cur][1][r]);
        }
#pragma unroll
        for (int tm = 0; tm < 2; tm++)
#pragma unroll
            for (int tn = 0; tn < 4; tn++) {
                mma16816(acc[tm][tn], ah[tm], bh[tn]);
                mma16816(acc[tm][tn], al[tm], bh[tn]);
                mma16816(acc[tm][tn], ah[tm], bl[tn]);
            }
        __syncthreads();
    }

    // epilogue: residual + bias
    int rr = lane >> 2, cc = (lane & 3) * 2;
#pragma unroll
    for (int tm = 0; tm < 2; tm++) {
#pragma unroll
        for (int tn = 0; tn < 4; tn++) {
            int gm = m0 + m_off + tm * 16 + rr;
            int gn = n0 + n_off + tn * 8 + cc;
            float2 bz = *(const float2*)(bias + gn);
            size_t i0 = (size_t)gm * DIMSZ + gn;
            float2 tk0 = *(const float2*)(tokens + i0);
            float2 o0 = { tk0.x + acc[tm][tn][0] + bz.x,
                          tk0.y + acc[tm][tn][1] + bz.y };
            *(float2*)(out + i0) = o0;
            size_t i1 = i0 + (size_t)8 * DIMSZ;
            float2 tk1 = *(const float2*)(tokens + i1);
            float2 o1 = { tk1.x + acc[tm][tn][2] + bz.x,
                          tk1.y + acc[tm][tn][3] + bz.y };
            *(float2*)(out + i1) = o1;
        }
    }
}

// ================== launch ==================
extern "C" void kernel_launch(void* const* d_in, const int* in_sizes, int n_in,
                              void* d_out, int out_size) {
    const float* tokens  = (const float*)d_in[0];
    const float* norm_w  = (const float*)d_in[1];
    const float* A_log   = (const float*)d_in[2];
    const float* log_dt  = (const float*)d_in[3];
    const float* B_in    = (const float*)d_in[4];
    const float* C_in    = (const float*)d_in[5];
    const float* D_in    = (const float*)d_in[6];
    const float* mixer_w = (const float*)d_in[7];
    const float* mixer_b = (const float*)d_in[8];
    float* out = (float*)d_out;

    prep_params_kernel<<<(DIMSZ * NST + 255) / 256, 256>>>(A_log, log_dt, B_in, C_in);
    prep_w_kernel<<<(DIMSZ * DIMSZ) / 256, 256>>>(mixer_w);
    rmsnorm_kernel<<<MROWS / 8, 256>>>(tokens, norm_w);
    scan_kernel<<<BATCH * 8, 256>>>(D_in);
    gemm_kernel<<<dim3(DIMSZ / 64, MROWS / 128), 256>>>(tokens, mixer_b, out);
}

// round 15
// speedup vs baseline: 1.1276x; 1.1276x over previous
#include <cuda_runtime.h>
#include <cuda_bf16.h>
#include <cstdint>

// Problem constants
#define BATCH   16
#define TSTEPS  4096
#define DIMSZ   512
#define NST     64
#define MROWS   (BATCH * TSTEPS)      // 65536

// ---------------- scratch (device globals: allocation-free) ----------------
__device__ float          g_rs  [MROWS];                            // 1/rms per row
__device__ __nv_bfloat16  g_yhi [(size_t)BATCH * TSTEPS * DIMSZ];
__device__ __nv_bfloat16  g_ylo [(size_t)BATCH * TSTEPS * DIMSZ];
__device__ float          g_A   [DIMSZ * NST];                      // A_bar
__device__ float          g_CB  [DIMSZ * NST];                      // C*B*dt
__device__ __nv_bfloat16  g_whi [DIMSZ * DIMSZ];
__device__ __nv_bfloat16  g_wlo [DIMSZ * DIMSZ];

// ---------------- packed f32x2 helpers ----------------
__device__ __forceinline__ unsigned long long pk2(float lo, float hi) {
    unsigned long long r;
    asm("mov.b64 %0, {%1,%2};" : "=l"(r) : "f"(lo), "f"(hi));
    return r;
}
__device__ __forceinline__ void upk2(unsigned long long v, float& lo, float& hi) {
    asm("mov.b64 {%0,%1}, %2;" : "=f"(lo), "=f"(hi) : "l"(v));
}
__device__ __forceinline__ unsigned long long mul2(unsigned long long a, unsigned long long b) {
    unsigned long long r;
    asm("mul.rn.f32x2 %0, %1, %2;" : "=l"(r) : "l"(a), "l"(b));
    return r;
}
__device__ __forceinline__ unsigned long long add2(unsigned long long a, unsigned long long b) {
    unsigned long long r;
    asm("add.rn.f32x2 %0, %1, %2;" : "=l"(r) : "l"(a), "l"(b));
    return r;
}
__device__ __forceinline__ unsigned long long fma2(unsigned long long a, unsigned long long b,
                                                   unsigned long long c) {
    unsigned long long r;
    asm("fma.rn.f32x2 %0, %1, %2, %3;" : "=l"(r) : "l"(a), "l"(b), "l"(c));
    return r;
}

// ---------------- cp.async / ldmatrix / mma helpers ----------------
__device__ __forceinline__ void cp16(void* dst, const void* src) {
    uint32_t d = (uint32_t)__cvta_generic_to_shared(dst);
    asm volatile("cp.async.cg.shared.global [%0], [%1], 16;\n" :: "r"(d), "l"(src) : "memory");
}
__device__ __forceinline__ void cp_commit() { asm volatile("cp.async.commit_group;\n" ::: "memory"); }
__device__ __forceinline__ void cp_wait1()  { asm volatile("cp.async.wait_group 1;\n" ::: "memory"); }
__device__ __forceinline__ void cp_wait0()  { asm volatile("cp.async.wait_group 0;\n" ::: "memory"); }

__device__ __forceinline__ void ldm_x4(uint32_t* r, const void* p) {
    uint32_t a = (uint32_t)__cvta_generic_to_shared(p);
    asm volatile("ldmatrix.sync.aligned.m8n8.x4.shared.b16 {%0,%1,%2,%3}, [%4];"
                 : "=r"(r[0]), "=r"(r[1]), "=r"(r[2]), "=r"(r[3]) : "r"(a));
}
__device__ __forceinline__ void ldm_x2(uint32_t* r, const void* p) {
    uint32_t a = (uint32_t)__cvta_generic_to_shared(p);
    asm volatile("ldmatrix.sync.aligned.m8n8.x2.shared.b16 {%0,%1}, [%2];"
                 : "=r"(r[0]), "=r"(r[1]) : "r"(a));
}
__device__ __forceinline__ void mma16816(float* c, const uint32_t* a, const uint32_t* b) {
    asm volatile("mma.sync.aligned.m16n8k16.row.col.f32.bf16.bf16.f32 "
                 "{%0,%1,%2,%3}, {%4,%5,%6,%7}, {%8,%9}, {%0,%1,%2,%3};"
                 : "+f"(c[0]), "+f"(c[1]), "+f"(c[2]), "+f"(c[3])
                 : "r"(a[0]), "r"(a[1]), "r"(a[2]), "r"(a[3]), "r"(b[0]), "r"(b[1]));
}

// ================== kernel 1: parameter discretization ==================
__global__ void __launch_bounds__(256)
prep_params_kernel(const float* __restrict__ A_log, const float* __restrict__ log_dt,
                   const float* __restrict__ B_in, const float* __restrict__ C_in) {
    int idx = blockIdx.x * 256 + threadIdx.x;      // 512*64 = 32768
    if (idx >= DIMSZ * NST) return;
    int d = idx >> 6;
    int n = idx & 63;
    float ld = log_dt[d];
    float dt = (ld > 15.f) ? ld : log1pf(expf(ld));   // softplus
    g_A[idx]  = expf(-dt * expf(A_log[idx]));
    g_CB[idx] = C_in[idx] * dt * B_in[n];
}

// ================== kernel 2: mixer weight bf16 split ==================
__global__ void __launch_bounds__(256)
prep_w_kernel(const float* __restrict__ W) {
    int idx = blockIdx.x * 256 + threadIdx.x;      // 262144
    float w = W[idx];
    __nv_bfloat16 h = __float2bfloat16(w);
    g_whi[idx] = h;
    g_wlo[idx] = __float2bfloat16(w - __bfloat162float(h));
}

// ================== kernel 3: RMS factors only ==================
__global__ void __launch_bounds__(256)
rms_kernel(const float* __restrict__ tokens) {
    int row  = blockIdx.x * 8 + (threadIdx.x >> 5);
    int lane = threadIdx.x & 31;
    const float* p = tokens + (size_t)row * DIMSZ;
    float ss = 0.f;
#pragma unroll
    for (int j = 0; j < 4; j++) {
        float4 v = *(const float4*)(p + lane * 4 + j * 128);
        ss += v.x * v.x + v.y * v.y + v.z * v.z + v.w * v.w;
    }
#pragma unroll
    for (int off = 16; off > 0; off >>= 1)
        ss += __shfl_xor_sync(0xffffffffu, ss, off);
    if (lane == 0)
        g_rs[row] = rsqrtf(ss * (1.0f / 512.0f) + 1e-4f);
}

// ================== kernel 4: the SSM scan ==================
// grid = 128 blocks (16 batches x 8 d-tiles of 64), 512 threads.
// thread: ch = tid>>3 (0..63), slot = tid&7 owns 8 of the 64 states.
// No shfl: each thread stores its scalar partial to SMEM; writer pass sums 8.
#define TC 64
#define SCAN_SMEM ((TC*64 + TC*64*8) * 4)     // xs + ps = 147456 bytes
__global__ void __launch_bounds__(512)
scan_kernel(const float* __restrict__ tokens, const float* __restrict__ nw,
            const float* __restrict__ Din) {
    extern __shared__ float ssm[];
    float* xs = ssm;                 // [TC][64]
    float* ps = ssm + TC * 64;       // [TC][64][8]

    int tid  = threadIdx.x;
    int b    = blockIdx.x >> 3;
    int d0   = (blockIdx.x & 7) << 6;
    int ch   = tid >> 3;
    int slot = tid & 7;
    int n0   = slot << 3;
    int d    = d0 + ch;

    unsigned long long a_[4], cb_[4], s_[4];
    const float2* ap = reinterpret_cast<const float2*>(g_A  + d * NST + n0);
    const float2* cp = reinterpret_cast<const float2*>(g_CB + d * NST + n0);
#pragma unroll
    for (int i = 0; i < 4; i++) {
        float2 t = ap[i]; a_[i]  = pk2(t.x, t.y);
        float2 u = cp[i]; cb_[i] = pk2(u.x, u.y);
        s_[i] = pk2(0.f, 0.f);
    }

    int cj = tid & 63;               // channel for copy/write phases
    int r0 = tid >> 6;               // 0..7
    float nwv = nw[d0 + cj];
    float dgv = Din[d0 + cj];
    const float* tokg = tokens + (size_t)b * TSTEPS * DIMSZ + d0;
    const float* rsg  = g_rs + (size_t)b * TSTEPS;
    size_t mbase = (size_t)b * TSTEPS;

    float* xcol  = xs + ch;          // stride 64 floats per step
    float* pscol = ps + ch * 8 + slot;  // stride 512 floats per step

    for (int t0 = 0; t0 < TSTEPS; t0 += TC) {
        // ---- load + normalize x chunk ----
#pragma unroll
        for (int i = 0; i < 8; i++) {
            int r = r0 + i * 8;
            float rv = __ldg(rsg + t0 + r);
            xs[r * 64 + cj] = tokg[(size_t)(t0 + r) * DIMSZ + cj] * (rv * nwv);
        }
        __syncthreads();

        // ---- recurrence: 8 states/thread, partial -> SMEM ----
#pragma unroll 8
        for (int tt = 0; tt < TC; tt++) {
            float xv = xcol[tt * 64];
            unsigned long long xx = pk2(xv, xv);
#pragma unroll
            for (int p = 0; p < 4; p++) {
                unsigned long long u = mul2(a_[p], s_[p]);
                s_[p] = fma2(cb_[p], xx, u);
            }
            unsigned long long t01 = add2(s_[0], s_[1]);
            unsigned long long t23 = add2(s_[2], s_[3]);
            unsigned long long tt2 = add2(t01, t23);
            float lo, hi;
            upk2(tt2, lo, hi);
            pscol[tt * 512] = lo + hi;
        }
        __syncthreads();

        // ---- writer: sum 8 partials + D*x, split to bf16 hi/lo ----
#pragma unroll
        for (int i = 0; i < 8; i++) {
            int r = r0 + i * 8;
            const float4* pq = reinterpret_cast<const float4*>(ps + (r * 64 + cj) * 8);
            float4 p0 = pq[0], p1 = pq[1];
            float acc = ((p0.x + p0.y) + (p0.z + p0.w)) +
                        ((p1.x + p1.y) + (p1.z + p1.w));
            float y = fmaf(dgv, xs[r * 64 + cj], acc);
            __nv_bfloat16 h = __float2bfloat16(y);
            __nv_bfloat16 l = __float2bfloat16(y - __bfloat162float(h));
            size_t idx = (mbase + t0 + r) * DIMSZ + d0 + cj;
            g_yhi[idx] = h;
            g_ylo[idx] = l;
        }
        __syncthreads();
    }
}

// ================== kernel 5: mixer GEMM (3-term bf16 split) + residual ==================
// BM=128, BN=128, BK=16, 3-stage cp.async, 256 threads, 8 warps (2 M x 4 N), warp 64x32
// sa: 3 stages x 2 (hi/lo) x 128 rows x 24 halfwords = 18432 bf16 = 36864 B; sb same.
#define GEMM_SMEM_BYTES (2 * 36864)
__global__ void __launch_bounds__(256)
gemm_kernel(const float* __restrict__ tokens, const float* __restrict__ bias,
            float* __restrict__ out) {
    extern __shared__ __nv_bfloat16 gsm[];
    __nv_bfloat16* sa = gsm;                    // [st][h][128][24]
    __nv_bfloat16* sb = gsm + 3 * 2 * 128 * 24;

    int tid = threadIdx.x;
    int m0 = blockIdx.y * 128;
    int n0 = blockIdx.x * 128;

    float acc[4][4][4];
#pragma unroll
    for (int i = 0; i < 4; i++)
#pragma unroll
        for (int j = 0; j < 4; j++)
#pragma unroll
            for (int k = 0; k < 4; k++) acc[i][j][k] = 0.f;

    int arow = tid >> 1, ach = tid & 1;         // 128 rows x 2 k-chunks
    size_t a_goff = (size_t)(m0 + arow) * DIMSZ + ach * 8;
    size_t b_goff = (size_t)(n0 + arow) * DIMSZ + ach * 8;
    int soff = arow * 24 + ach * 8;

    auto load_st = [&](int st, int k0) {
        cp16(&sa[(st * 2 + 0) * 128 * 24 + soff], g_yhi + a_goff + k0);
        cp16(&sa[(st * 2 + 1) * 128 * 24 + soff], g_ylo + a_goff + k0);
        cp16(&sb[(st * 2 + 0) * 128 * 24 + soff], g_whi + b_goff + k0);
        cp16(&sb[(st * 2 + 1) * 128 * 24 + soff], g_wlo + b_goff + k0);
        cp_commit();
    };
    load_st(0, 0);
    load_st(1, 16);

    int lane = tid & 31;
    int wid  = tid >> 5;
    int m_off = (wid & 1) * 64;
    int n_off = (wid >> 1) * 32;
    int a_lrow = lane & 15, a_lk = (lane >> 4) * 8;
    int b_lrow = lane & 7,  b_lk = ((lane >> 3) & 1) * 8;

    for (int kt = 0; kt < 32; kt++) {
        if (kt < 30) cp_wait1(); else cp_wait0();
        __syncthreads();
        if (kt < 30) load_st((kt + 2) % 3, (kt + 2) * 16);

        int st = kt % 3;
        uint32_t ah[4][4], al[4][4], bh[4][2], bl[4][2];
#pragma unroll
        for (int tm = 0; tm < 4; tm++) {
            int r = (m_off + tm * 16 + a_lrow) * 24 + a_lk;
            ldm_x4(ah[tm], &sa[(st * 2 + 0) * 128 * 24 + r]);
            ldm_x4(al[tm], &sa[(st * 2 + 1) * 128 * 24 + r]);
        }
#pragma unroll
        for (int tn = 0; tn < 4; tn++) {
            int r = (n_off + tn * 8 + b_lrow) * 24 + b_lk;
            ldm_x2(bh[tn], &sb[(st * 2 + 0) * 128 * 24 + r]);
            ldm_x2(bl[tn], &sb[(st * 2 + 1) * 128 * 24 + r]);
        }
#pragma unroll
        for (int tm = 0; tm < 4; tm++)
#pragma unroll
            for (int tn = 0; tn < 4; tn++) {
                mma16816(acc[tm][tn], ah[tm], bh[tn]);
                mma16816(acc[tm][tn], al[tm], bh[tn]);
                mma16816(acc[tm][tn], ah[tm], bl[tn]);
            }
    }

    // epilogue: residual + bias
    int rr = lane >> 2, cc = (lane & 3) * 2;
#pragma unroll
    for (int tm = 0; tm < 4; tm++) {
#pragma unroll
        for (int tn = 0; tn < 4; tn++) {
            int gm = m0 + m_off + tm * 16 + rr;
            int gn = n0 + n_off + tn * 8 + cc;
            float2 bz = *(const float2*)(bias + gn);
            size_t i0 = (size_t)gm * DIMSZ + gn;
            float2 tk0 = *(const float2*)(tokens + i0);
            float2 o0 = { tk0.x + acc[tm][tn][0] + bz.x,
                          tk0.y + acc[tm][tn][1] + bz.y };
            *(float2*)(out + i0) = o0;
            size_t i1 = i0 + (size_t)8 * DIMSZ;
            float2 tk1 = *(const float2*)(tokens + i1);
            float2 o1 = { tk1.x + acc[tm][tn][2] + bz.x,
                          tk1.y + acc[tm][tn][3] + bz.y };
            *(float2*)(out + i1) = o1;
        }
    }
}

// ================== launch ==================
extern "C" void kernel_launch(void* const* d_in, const int* in_sizes, int n_in,
                              void* d_out, int out_size) {
    const float* tokens  = (const float*)d_in[0];
    const float* norm_w  = (const float*)d_in[1];
    const float* A_log   = (const float*)d_in[2];
    const float* log_dt  = (const float*)d_in[3];
    const float* B_in    = (const float*)d_in[4];
    const float* C_in    = (const float*)d_in[5];
    const float* D_in    = (const float*)d_in[6];
    const float* mixer_w = (const float*)d_in[7];
    const float* mixer_b = (const float*)d_in[8];
    float* out = (float*)d_out;

    cudaFuncSetAttribute(scan_kernel, cudaFuncAttributeMaxDynamicSharedMemorySize, SCAN_SMEM);
    cudaFuncSetAttribute(gemm_kernel, cudaFuncAttributeMaxDynamicSharedMemorySize, GEMM_SMEM_BYTES);

    prep_params_kernel<<<(DIMSZ * NST + 255) / 256, 256>>>(A_log, log_dt, B_in, C_in);
    prep_w_kernel<<<(DIMSZ * DIMSZ) / 256, 256>>>(mixer_w);
    rms_kernel<<<MROWS / 8, 256>>>(tokens);
    scan_kernel<<<BATCH * 8, 512, SCAN_SMEM>>>(tokens, norm_w, D_in);
    gemm_kernel<<<dim3(DIMSZ / 128, MROWS / 128), 256, GEMM_SMEM_BYTES>>>(tokens, mixer_b, out);
}